// round 5
// baseline (speedup 1.0000x reference)
#include <cuda_runtime.h>
#include <math.h>

#define NN   50000
#define EE   800000
#define GG   2000
#define FIN  34
#define HIDW 256
#define NH   8
#define HD   32
#define NL   5
#define E2   (EE + NN)

// ---------------- scratch (device globals; no allocation allowed) ----------------
__device__ float g_h [NN * HIDW];
__device__ float g_b1[NN * HIDW];
__device__ float g_b2[NN * HIDW];
__device__ float g_b3[NN * HIDW];
__device__ float g_b4[NN * HIDW];
__device__ float g_sc[E2 * NH];
__device__ float g_m  [NN * NH];
__device__ float g_den[NN * NH];
__device__ float g_psum[GG * HIDW];
__device__ float g_pmax[GG * HIDW];
__device__ float g_cnt [GG];
__device__ float g_ge[GG * 2 * HIDW];
__device__ float g_go[GG * 2 * HIDW];

// ---------------- helpers ----------------
__device__ __forceinline__ void atomicMaxFloat(float* addr, float val) {
    int* ai = (int*)addr;
    int old = *ai;
    while (__int_as_float(old) < val) {
        int assumed = old;
        old = atomicCAS(ai, assumed, __float_as_int(val));
        if (old == assumed) break;
    }
}

__device__ __forceinline__ float warpSum(float v) {
#pragma unroll
    for (int o = 16; o > 0; o >>= 1) v += __shfl_xor_sync(0xffffffffu, v, o);
    return v;
}

__device__ __forceinline__ float gelu_exact(float x) {
    return 0.5f * x * (1.0f + erff(x * 0.70710678118654752440f));
}

// ---------------- GEMM: C[M,Ncol] = A[M,K] @ W[K,Ncol] + bias ----------------
#define BM 64
#define BN 64
#define BK 16
#define TM 4
#define TN 4

__global__ __launch_bounds__(256)
void gemm_bias(const float* __restrict__ A, const float* __restrict__ W,
               const float* __restrict__ bias, float* __restrict__ C,
               int M, int K, int Ncol)
{
    __shared__ float As[BK][BM];
    __shared__ float Bs[BK][BN];
    int bx = blockIdx.x * BN, by = blockIdx.y * BM;
    int tid = threadIdx.x;
    int tr = tid / 16, tc = tid % 16;
    float acc[TM][TN] = {};

    for (int k0 = 0; k0 < K; k0 += BK) {
        for (int i = tid; i < BM * BK; i += 256) {
            int m = i / BK, kk = i % BK;
            int gm = by + m, gk = k0 + kk;
            As[kk][m] = (gm < M && gk < K) ? A[(size_t)gm * K + gk] : 0.f;
        }
        for (int i = tid; i < BK * BN; i += 256) {
            int kk = i / BN, n = i % BN;
            int gk = k0 + kk, gn = bx + n;
            Bs[kk][n] = (gk < K) ? W[(size_t)gk * Ncol + gn] : 0.f;
        }
        __syncthreads();
#pragma unroll
        for (int kk = 0; kk < BK; kk++) {
            float a[TM], b[TN];
#pragma unroll
            for (int i = 0; i < TM; i++) a[i] = As[kk][tr * TM + i];
#pragma unroll
            for (int j = 0; j < TN; j++) b[j] = Bs[kk][tc * TN + j];
#pragma unroll
            for (int i = 0; i < TM; i++)
#pragma unroll
                for (int j = 0; j < TN; j++) acc[i][j] += a[i] * b[j];
        }
        __syncthreads();
    }
#pragma unroll
    for (int i = 0; i < TM; i++) {
        int gm = by + tr * TM + i;
        if (gm >= M) continue;
#pragma unroll
        for (int j = 0; j < TN; j++) {
            int gn = bx + tc * TN + j;
            C[(size_t)gm * Ncol + gn] = acc[i][j] + bias[gn];
        }
    }
}

// ---------------- fused: out = [resid +] (gelu?)(LN(x [+x2] [+colbias])) ----------------
__global__ void ln_act_kernel(const float* __restrict__ x, const float* __restrict__ x2,
                              const float* __restrict__ colbias,
                              const float* __restrict__ gamma, const float* __restrict__ beta,
                              const float* __restrict__ resid, float* __restrict__ out,
                              int rows, int width, int do_gelu)
{
    int warp = (blockIdx.x * blockDim.x + threadIdx.x) >> 5;
    int lane = threadIdx.x & 31;
    if (warp >= rows) return;
    const int per = width / 32;           // 8 or 16
    float v[16];
    size_t base = (size_t)warp * width;
    float s = 0.f, ss = 0.f;
#pragma unroll 4
    for (int i = 0; i < per; i++) {
        int c = lane + i * 32;
        float t = x[base + c];
        if (x2)      t += x2[base + c];
        if (colbias) t += colbias[c];
        v[i] = t; s += t; ss += t * t;
    }
    s  = warpSum(s);
    ss = warpSum(ss);
    float mean = s / width;
    float var  = ss / width - mean * mean;
    float inv  = rsqrtf(var + 1e-5f);
#pragma unroll 4
    for (int i = 0; i < per; i++) {
        int c = lane + i * 32;
        float t = (v[i] - mean) * inv * gamma[c] + beta[c];
        if (do_gelu) t = gelu_exact(t);
        if (resid)   t += resid[base + c];
        out[base + c] = t;
    }
}

// ---------------- GATv2 edge score + segment max (self loops appended) ----------------
__global__ void gat_score_kernel(const float* __restrict__ xl, const float* __restrict__ xr,
                                 const int* __restrict__ src, const int* __restrict__ dst,
                                 const float* __restrict__ att,
                                 float* __restrict__ sc, float* __restrict__ m)
{
    int e = (blockIdx.x * blockDim.x + threadIdx.x) >> 5;
    int lane = threadIdx.x & 31;
    if (e >= E2) return;
    int s = (e < EE) ? src[e] : (e - EE);
    int d = (e < EE) ? dst[e] : (e - EE);
    const float* pl = xl + (size_t)s * HIDW;
    const float* pr = xr + (size_t)d * HIDW;
#pragma unroll
    for (int h = 0; h < NH; h++) {
        float a = pl[h * HD + lane] + pr[h * HD + lane];
        a = a > 0.f ? a : 0.2f * a;
        float p = warpSum(a * att[h * HD + lane]);
        if (lane == 0) {
            sc[(size_t)e * NH + h] = p;
            atomicMaxFloat(&m[d * NH + h], p);
        }
    }
}

// ---------------- TransformerConv edge score ----------------
__global__ void tr_score_kernel(const float* __restrict__ q, const float* __restrict__ k,
                                const int* __restrict__ src, const int* __restrict__ dst,
                                float* __restrict__ sc, float* __restrict__ m)
{
    int e = (blockIdx.x * blockDim.x + threadIdx.x) >> 5;
    int lane = threadIdx.x & 31;
    if (e >= EE) return;
    int s = src[e], d = dst[e];
    const float* pq = q + (size_t)d * HIDW;
    const float* pk = k + (size_t)s * HIDW;
#pragma unroll
    for (int h = 0; h < NH; h++) {
        float p = warpSum(pq[h * HD + lane] * pk[h * HD + lane]);
        p *= 0.17677669529663688f;  // 1/sqrt(32)
        if (lane == 0) {
            sc[(size_t)e * NH + h] = p;
            atomicMaxFloat(&m[d * NH + h], p);
        }
    }
}

// ---------------- exp(score - max), accumulate denominator ----------------
__global__ void exden_kernel(const int* __restrict__ dst, float* __restrict__ sc,
                             const float* __restrict__ m, float* __restrict__ den,
                             int nedge, int with_loops)
{
    int idx = blockIdx.x * blockDim.x + threadIdx.x;
    if (idx >= nedge * NH) return;
    int e = idx >> 3, h = idx & 7;
    int d = (with_loops && e >= EE) ? (e - EE) : dst[e];
    float mv = m[d * NH + h];
    if (!isfinite(mv)) mv = 0.f;
    float ex = expf(sc[idx] - mv);
    sc[idx] = ex;
    atomicAdd(&den[d * NH + h], ex);
}

// ---------------- weighted aggregation (atomic scatter) ----------------
__global__ void agg_kernel(const float* __restrict__ val,
                           const int* __restrict__ src, const int* __restrict__ dst,
                           const float* __restrict__ ex, const float* __restrict__ den,
                           float* __restrict__ out, int nedge, int with_loops)
{
    int e = (blockIdx.x * blockDim.x + threadIdx.x) >> 5;
    int lane = threadIdx.x & 31;
    if (e >= nedge) return;
    int s, d;
    if (with_loops && e >= EE) { s = d = e - EE; }
    else { s = src[e]; d = dst[e]; }
    const float* pv = val + (size_t)s * HIDW;
    float* po = out + (size_t)d * HIDW;
#pragma unroll
    for (int h = 0; h < NH; h++) {
        float alpha = ex[(size_t)e * NH + h] / (den[d * NH + h] + 1e-16f);
        atomicAdd(&po[h * HD + lane], pv[h * HD + lane] * alpha);
    }
}

// ---------------- pooling ----------------
__global__ void pool_kernel(const float* __restrict__ h, const int* __restrict__ batch,
                            float* __restrict__ psum, float* __restrict__ pmax,
                            float* __restrict__ cnt)
{
    int idx = blockIdx.x * blockDim.x + threadIdx.x;
    if (idx >= NN * HIDW) return;
    int n = idx >> 8, f = idx & 255;
    int g = batch[n];
    float v = h[idx];
    atomicAdd(&psum[g * HIDW + f], v);
    atomicMaxFloat(&pmax[g * HIDW + f], v);
    if (f == 0) atomicAdd(&cnt[g], 1.f);
}

__global__ void ge_kernel(const float* __restrict__ psum, const float* __restrict__ pmax,
                          const float* __restrict__ cnt, float* __restrict__ ge)
{
    int idx = blockIdx.x * blockDim.x + threadIdx.x;
    if (idx >= GG * 2 * HIDW) return;
    int g = idx >> 9, f = idx & 511;
    float o;
    if (f < HIDW) {
        o = psum[g * HIDW + f] / fmaxf(cnt[g], 1.f);
    } else {
        o = pmax[g * HIDW + f - HIDW];
        if (!isfinite(o)) o = 0.f;
    }
    ge[idx] = o;
}

__global__ void fill_kernel(float* __restrict__ p, float v, int n)
{
    int i = blockIdx.x * blockDim.x + threadIdx.x;
    if (i < n) p[i] = v;
}

// ---------------- host orchestration ----------------
extern "C" void kernel_launch(void* const* d_in, const int* in_sizes, int n_in,
                              void* d_out, int out_size)
{
    const float* x       = (const float*)d_in[0];
    const int*   ei      = (const int*)  d_in[1];
    const int*   batch   = (const int*)  d_in[2];
    const float* in_W    = (const float*)d_in[3];
    const float* in_b    = (const float*)d_in[4];
    const float* in_ln_g = (const float*)d_in[5];
    const float* in_ln_b = (const float*)d_in[6];
    const float* gat_Wl  = (const float*)d_in[7];
    const float* gat_bl  = (const float*)d_in[8];
    const float* gat_Wr  = (const float*)d_in[9];
    const float* gat_br  = (const float*)d_in[10];
    const float* gat_att = (const float*)d_in[11];
    const float* gat_bias= (const float*)d_in[12];
    const float* gat_ln_g= (const float*)d_in[13];
    const float* gat_ln_b= (const float*)d_in[14];
    const float* tr_Wq   = (const float*)d_in[15];
    const float* tr_bq   = (const float*)d_in[16];
    const float* tr_Wk   = (const float*)d_in[17];
    const float* tr_bk   = (const float*)d_in[18];
    const float* tr_Wv   = (const float*)d_in[19];
    const float* tr_bv   = (const float*)d_in[20];
    const float* tr_Wskip= (const float*)d_in[21];
    const float* tr_bskip= (const float*)d_in[22];
    const float* tr_ln_g = (const float*)d_in[23];
    const float* tr_ln_b = (const float*)d_in[24];
    const float* out_W   = (const float*)d_in[25];
    const float* out_b   = (const float*)d_in[26];
    const float* out_ln_g= (const float*)d_in[27];
    const float* out_ln_b= (const float*)d_in[28];

    const int* src = ei;
    const int* dst = ei + EE;

    float *h, *b1, *b2, *b3, *b4, *sc, *m, *den, *psum, *pmax, *cnt, *ge, *go;
    cudaGetSymbolAddress((void**)&h,   g_h);
    cudaGetSymbolAddress((void**)&b1,  g_b1);
    cudaGetSymbolAddress((void**)&b2,  g_b2);
    cudaGetSymbolAddress((void**)&b3,  g_b3);
    cudaGetSymbolAddress((void**)&b4,  g_b4);
    cudaGetSymbolAddress((void**)&sc,  g_sc);
    cudaGetSymbolAddress((void**)&m,   g_m);
    cudaGetSymbolAddress((void**)&den, g_den);
    cudaGetSymbolAddress((void**)&psum,g_psum);
    cudaGetSymbolAddress((void**)&pmax,g_pmax);
    cudaGetSymbolAddress((void**)&cnt, g_cnt);
    cudaGetSymbolAddress((void**)&ge,  g_ge);
    cudaGetSymbolAddress((void**)&go,  g_go);

    const int ROW_WARPS_N  = (NN * 32 + 255) / 256;   // 1 warp per node row
    const int EDGE_WARPS2  = (E2 * 32 + 255) / 256;   // 1 warp per edge (with loops)
    const int EDGE_WARPS   = (EE * 32 + 255) / 256;

    // ---- input embedding: h = gelu(LN(x @ in_W + in_b)) ----
    gemm_bias<<<dim3(HIDW / BN, (NN + BM - 1) / BM), 256>>>(x, in_W, in_b, b1, NN, FIN, HIDW);
    ln_act_kernel<<<ROW_WARPS_N, 256>>>(b1, nullptr, nullptr, in_ln_g, in_ln_b,
                                        nullptr, h, NN, HIDW, 1);

    // ---- 5 GATv2 layers ----
    for (int l = 0; l < NL; l++) {
        const float* Wl = gat_Wl + (size_t)l * HIDW * HIDW;
        const float* Wr = gat_Wr + (size_t)l * HIDW * HIDW;
        gemm_bias<<<dim3(HIDW / BN, (NN + BM - 1) / BM), 256>>>(h, Wl, gat_bl + l * HIDW, b1, NN, HIDW, HIDW);
        gemm_bias<<<dim3(HIDW / BN, (NN + BM - 1) / BM), 256>>>(h, Wr, gat_br + l * HIDW, b2, NN, HIDW, HIDW);

        fill_kernel<<<(NN * NH + 255) / 256, 256>>>(m, -INFINITY, NN * NH);
        cudaMemsetAsync(den, 0, (size_t)NN * NH * sizeof(float));

        gat_score_kernel<<<EDGE_WARPS2, 256>>>(b1, b2, src, dst,
                                               gat_att + (size_t)l * NH * HD, sc, m);
        exden_kernel<<<(E2 * NH + 255) / 256, 256>>>(dst, sc, m, den, E2, 1);

        cudaMemsetAsync(b3, 0, (size_t)NN * HIDW * sizeof(float));
        agg_kernel<<<EDGE_WARPS2, 256>>>(b1, src, dst, sc, den, b3, E2, 1);

        // h = h + gelu(LN(agg + gat_bias[l]))
        ln_act_kernel<<<ROW_WARPS_N, 256>>>(b3, nullptr, gat_bias + l * HIDW,
                                            gat_ln_g + l * HIDW, gat_ln_b + l * HIDW,
                                            h, h, NN, HIDW, 1);
    }

    // ---- TransformerConv ----
    gemm_bias<<<dim3(HIDW / BN, (NN + BM - 1) / BM), 256>>>(h, tr_Wq, tr_bq, b1, NN, HIDW, HIDW);
    gemm_bias<<<dim3(HIDW / BN, (NN + BM - 1) / BM), 256>>>(h, tr_Wk, tr_bk, b2, NN, HIDW, HIDW);
    gemm_bias<<<dim3(HIDW / BN, (NN + BM - 1) / BM), 256>>>(h, tr_Wv, tr_bv, b3, NN, HIDW, HIDW);

    fill_kernel<<<(NN * NH + 255) / 256, 256>>>(m, -INFINITY, NN * NH);
    cudaMemsetAsync(den, 0, (size_t)NN * NH * sizeof(float));

    tr_score_kernel<<<EDGE_WARPS, 256>>>(b1, b2, src, dst, sc, m);
    exden_kernel<<<(EE * NH + 255) / 256, 256>>>(dst, sc, m, den, EE, 0);

    cudaMemsetAsync(b4, 0, (size_t)NN * HIDW * sizeof(float));
    agg_kernel<<<EDGE_WARPS, 256>>>(b3, src, dst, sc, den, b4, EE, 0);

    gemm_bias<<<dim3(HIDW / BN, (NN + BM - 1) / BM), 256>>>(h, tr_Wskip, tr_bskip, b1, NN, HIDW, HIDW);

    // h = h + LN(agg + skip)
    ln_act_kernel<<<ROW_WARPS_N, 256>>>(b4, b1, nullptr, tr_ln_g, tr_ln_b,
                                        h, h, NN, HIDW, 0);

    // ---- global mean + max pool ----
    cudaMemsetAsync(psum, 0, (size_t)GG * HIDW * sizeof(float));
    cudaMemsetAsync(cnt,  0, (size_t)GG * sizeof(float));
    fill_kernel<<<(GG * HIDW + 255) / 256, 256>>>(pmax, -INFINITY, GG * HIDW);
    pool_kernel<<<(NN * HIDW + 255) / 256, 256>>>(h, batch, psum, pmax, cnt);
    ge_kernel<<<(GG * 2 * HIDW + 255) / 256, 256>>>(psum, pmax, cnt, ge);

    // ---- output projection: gelu(LN(ge @ out_W + out_b)) ----
    gemm_bias<<<dim3(2 * HIDW / BN, (GG + BM - 1) / BM), 256>>>(ge, out_W, out_b, go, GG, 2 * HIDW, 2 * HIDW);
    ln_act_kernel<<<(GG * 32 + 255) / 256, 256>>>(go, nullptr, nullptr, out_ln_g, out_ln_b,
                                                  nullptr, (float*)d_out, GG, 2 * HIDW, 1);
}

// round 9
// speedup vs baseline: 3.2522x; 3.2522x over previous
#include <cuda_runtime.h>
#include <math.h>

#define NN   50000
#define EE   800000
#define GG   2000
#define FIN  34
#define HIDW 256
#define NH   8
#define HD   32
#define NL   5

// ---------------- scratch (device globals; no allocation allowed) ----------------
__device__ float g_h [NN * HIDW];
__device__ float g_b1[NN * HIDW];
__device__ float g_b2[NN * HIDW];
__device__ float g_b3[NN * HIDW];
__device__ float g_b4[NN * HIDW];
__device__ float g_sc[(size_t)EE * NH];
__device__ float g_ge[GG * 2 * HIDW];
__device__ float g_go[GG * 2 * HIDW];

// CSR scratch
__device__ int g_deg[NN];
__device__ int g_rowptr[NN];
__device__ int g_cur[NN];      // after scatter: row end
__device__ int g_bsum[256];
__device__ int g_ecol[EE];
__device__ int g_esrc[EE];

// ---------------- helpers ----------------
__device__ __forceinline__ float warpSum(float v) {
#pragma unroll
    for (int o = 16; o > 0; o >>= 1) v += __shfl_xor_sync(0xffffffffu, v, o);
    return v;
}

__device__ __forceinline__ float gelu_exact(float x) {
    return 0.5f * x * (1.0f + erff(x * 0.70710678118654752440f));
}

// ---------------- GEMM: C[M,Ncol] = A[M,K] @ W[K,Ncol] + bias ----------------
// 128x128x16 block tile, 8x8 thread tile, 256 threads.
#define BM 128
#define BN 128
#define BKK 16

__global__ __launch_bounds__(256, 2)
void gemm_bias(const float* __restrict__ A, const float* __restrict__ W,
               const float* __restrict__ bias, float* __restrict__ C,
               int M, int K, int Ncol)
{
    __shared__ float As[BKK][BM + 4];
    __shared__ float Bs[BKK][BN];
    int bx = blockIdx.x * BN, by = blockIdx.y * BM;
    int tid = threadIdx.x;
    int tr = tid >> 4, tc = tid & 15;
    float acc[8][8] = {};
    const bool vec = ((K & 15) == 0);

    for (int k0 = 0; k0 < K; k0 += BKK) {
        if (vec) {
#pragma unroll
            for (int r = 0; r < 2; r++) {
                int i = tid + r * 256;            // i < 512
                int m = i >> 2, c4 = i & 3;
                int gm = by + m;
                float4 a = (gm < M) ? *(const float4*)(A + (size_t)gm * K + k0 + c4 * 4)
                                    : make_float4(0.f, 0.f, 0.f, 0.f);
                As[c4 * 4 + 0][m] = a.x;
                As[c4 * 4 + 1][m] = a.y;
                As[c4 * 4 + 2][m] = a.z;
                As[c4 * 4 + 3][m] = a.w;
            }
#pragma unroll
            for (int r = 0; r < 2; r++) {
                int i = tid + r * 256;
                int kk = i >> 5, n4 = i & 31;
                *(float4*)&Bs[kk][n4 * 4] =
                    *(const float4*)(W + (size_t)(k0 + kk) * Ncol + bx + n4 * 4);
            }
        } else {
            for (int i = tid; i < BM * BKK; i += 256) {
                int m = i >> 4, kk = i & 15;
                int gm = by + m, gk = k0 + kk;
                As[kk][m] = (gm < M && gk < K) ? A[(size_t)gm * K + gk] : 0.f;
            }
            for (int i = tid; i < BKK * BN; i += 256) {
                int kk = i >> 7, n = i & 127;
                int gk = k0 + kk;
                Bs[kk][n] = (gk < K) ? W[(size_t)gk * Ncol + bx + n] : 0.f;
            }
        }
        __syncthreads();
#pragma unroll
        for (int kk = 0; kk < BKK; kk++) {
            float a[8], b[8];
            *(float4*)&a[0] = *(const float4*)&As[kk][tr * 4];
            *(float4*)&a[4] = *(const float4*)&As[kk][64 + tr * 4];
            *(float4*)&b[0] = *(const float4*)&Bs[kk][tc * 4];
            *(float4*)&b[4] = *(const float4*)&Bs[kk][64 + tc * 4];
#pragma unroll
            for (int i = 0; i < 8; i++)
#pragma unroll
                for (int j = 0; j < 8; j++) acc[i][j] += a[i] * b[j];
        }
        __syncthreads();
    }
#pragma unroll
    for (int i = 0; i < 8; i++) {
        int gm = by + ((i < 4) ? (tr * 4 + i) : (64 + tr * 4 + i - 4));
        if (gm >= M) continue;
#pragma unroll
        for (int jh = 0; jh < 2; jh++) {
            int gn = bx + jh * 64 + tc * 4;
            float4 o;
            o.x = acc[i][jh * 4 + 0] + bias[gn + 0];
            o.y = acc[i][jh * 4 + 1] + bias[gn + 1];
            o.z = acc[i][jh * 4 + 2] + bias[gn + 2];
            o.w = acc[i][jh * 4 + 3] + bias[gn + 3];
            *(float4*)(C + (size_t)gm * Ncol + gn) = o;
        }
    }
}

// ---------------- fused: out = (gelu?)(LN(x)) (embed + final only) ----------------
__global__ void ln_act_kernel(const float* __restrict__ x,
                              const float* __restrict__ gamma, const float* __restrict__ beta,
                              float* __restrict__ out,
                              int rows, int width, int do_gelu)
{
    int warp = (blockIdx.x * blockDim.x + threadIdx.x) >> 5;
    int lane = threadIdx.x & 31;
    if (warp >= rows) return;
    const int per = width / 32;
    float v[16];
    size_t base = (size_t)warp * width;
    float s = 0.f, ss = 0.f;
#pragma unroll 4
    for (int i = 0; i < per; i++) {
        float t = x[base + lane + i * 32];
        v[i] = t; s += t; ss += t * t;
    }
    s = warpSum(s); ss = warpSum(ss);
    float mean = s / width;
    float inv = rsqrtf(ss / width - mean * mean + 1e-5f);
#pragma unroll 4
    for (int i = 0; i < per; i++) {
        int c = lane + i * 32;
        float t = (v[i] - mean) * inv * gamma[c] + beta[c];
        if (do_gelu) t = gelu_exact(t);
        out[base + c] = t;
    }
}

// ---------------- CSR build ----------------
__global__ void hist_kernel(const int* __restrict__ dst, int* __restrict__ deg) {
    int e = blockIdx.x * blockDim.x + threadIdx.x;
    if (e < EE) atomicAdd(&deg[dst[e]], 1);
}

#define SCH 256
#define SNB ((NN + SCH - 1) / SCH)     // 196

__global__ void scan1_kernel(const int* __restrict__ deg, int* __restrict__ rowptr,
                             int* __restrict__ bsum) {
    __shared__ int s[SCH];
    int b = blockIdx.x, t = threadIdx.x;
    int i = b * SCH + t;
    int v = (i < NN) ? deg[i] : 0;
    s[t] = v; __syncthreads();
    for (int o = 1; o < SCH; o <<= 1) {
        int x = (t >= o) ? s[t - o] : 0;
        __syncthreads();
        s[t] += x;
        __syncthreads();
    }
    if (i < NN) rowptr[i] = s[t] - v;
    if (t == SCH - 1) bsum[b] = s[t];
}

__global__ void scan2_kernel(int* __restrict__ bsum) {
    __shared__ int s[256];
    int t = threadIdx.x;
    int v = (t < SNB) ? bsum[t] : 0;
    s[t] = v; __syncthreads();
    for (int o = 1; o < 256; o <<= 1) {
        int x = (t >= o) ? s[t - o] : 0;
        __syncthreads();
        s[t] += x;
        __syncthreads();
    }
    if (t < SNB) bsum[t] = s[t] - v;
}

__global__ void scan3_kernel(int* __restrict__ rowptr, const int* __restrict__ bsum,
                             int* __restrict__ cur) {
    int i = blockIdx.x * blockDim.x + threadIdx.x;
    if (i < NN) {
        int r = rowptr[i] + bsum[i / SCH];
        rowptr[i] = r;
        cur[i] = r;
    }
}

__global__ void scatter_kernel(const int* __restrict__ src, const int* __restrict__ dst,
                               int* __restrict__ cur, int* __restrict__ ecol,
                               int* __restrict__ esrc) {
    int e = blockIdx.x * blockDim.x + threadIdx.x;
    if (e < EE) {
        int d = dst[e];
        int p = atomicAdd(&cur[d], 1);
        ecol[p] = e;
        esrc[p] = src[e];
    }
}

// ---------------- per-edge score kernels (write sc only) ----------------
__global__ void gat_score_kernel(const float* __restrict__ xl, const float* __restrict__ xr,
                                 const int* __restrict__ src, const int* __restrict__ dst,
                                 const float* __restrict__ att, float* __restrict__ sc)
{
    int e = (blockIdx.x * blockDim.x + threadIdx.x) >> 5;
    int lane = threadIdx.x & 31;
    if (e >= EE) return;
    const float* pl = xl + (size_t)src[e] * HIDW;
    const float* pr = xr + (size_t)dst[e] * HIDW;
#pragma unroll
    for (int h = 0; h < NH; h++) {
        float a = pl[h * HD + lane] + pr[h * HD + lane];
        a = a > 0.f ? a : 0.2f * a;
        float p = warpSum(a * att[h * HD + lane]);
        if (lane == h) sc[(size_t)e * NH + h] = p;
    }
}

__global__ void tr_score_kernel(const float* __restrict__ q, const float* __restrict__ k,
                                const int* __restrict__ src, const int* __restrict__ dst,
                                float* __restrict__ sc)
{
    int e = (blockIdx.x * blockDim.x + threadIdx.x) >> 5;
    int lane = threadIdx.x & 31;
    if (e >= EE) return;
    const float* pq = q + (size_t)dst[e] * HIDW;
    const float* pk = k + (size_t)src[e] * HIDW;
#pragma unroll
    for (int h = 0; h < NH; h++) {
        float p = warpSum(pq[h * HD + lane] * pk[h * HD + lane]) * 0.17677669529663688f;
        if (lane == h) sc[(size_t)e * NH + h] = p;
    }
}

// ---------------- GATv2 node kernel: softmax + aggregate + bias + LN + GELU + residual ----
__global__ void gat_node_kernel(const float* __restrict__ xl, const float* __restrict__ xr,
                                const float* __restrict__ sc,
                                const int* __restrict__ rowptr, const int* __restrict__ rowend,
                                const int* __restrict__ ecol, const int* __restrict__ esrc,
                                const float* __restrict__ att,
                                const float* __restrict__ colbias,
                                const float* __restrict__ gamma, const float* __restrict__ beta,
                                float* __restrict__ hbuf)
{
    int d = (blockIdx.x * blockDim.x + threadIdx.x) >> 5;
    int lane = threadIdx.x & 31;
    if (d >= NN) return;
    int r0 = rowptr[d], r1 = rowend[d];
    const float* pl = xl + (size_t)d * HIDW;
    const float* pr = xr + (size_t)d * HIDW;

    // self-loop score
    float sself = 0.f;
#pragma unroll
    for (int h = 0; h < NH; h++) {
        float a = pl[h * HD + lane] + pr[h * HD + lane];
        a = a > 0.f ? a : 0.2f * a;
        float p = warpSum(a * att[h * HD + lane]);
        if (lane == h) sself = p;
    }
    // max over incoming edges + self (per head, held in lanes 0..7)
    float mx = (lane < NH) ? sself : -INFINITY;
    for (int i = r0; i < r1; i++) {
        int e = ecol[i];
        float v = sc[(size_t)e * NH + (lane & 7)];
        if (lane < NH) mx = fmaxf(mx, v);
    }
    // aggregate (unnormalized) + denominator
    float exself = (lane < NH) ? expf(sself - mx) : 0.f;
    float den = exself;
    float acc[NH];
#pragma unroll
    for (int h = 0; h < NH; h++)
        acc[h] = __shfl_sync(0xffffffffu, exself, h) * pl[h * HD + lane];
    for (int i = r0; i < r1; i++) {
        int e = ecol[i], s = esrc[i];
        float raw = sc[(size_t)e * NH + (lane & 7)];
        float ev = (lane < NH) ? expf(raw - mx) : 0.f;
        den += ev;
        const float* pv = xl + (size_t)s * HIDW;
#pragma unroll
        for (int h = 0; h < NH; h++)
            acc[h] += __shfl_sync(0xffffffffu, ev, h) * pv[h * HD + lane];
    }
    // normalize + bias, then LN + GELU + residual
    float s1 = 0.f, s2 = 0.f;
#pragma unroll
    for (int h = 0; h < NH; h++) {
        float dh = __shfl_sync(0xffffffffu, den, h) + 1e-16f;
        float t = acc[h] / dh + colbias[h * HD + lane];
        acc[h] = t; s1 += t; s2 += t * t;
    }
    s1 = warpSum(s1); s2 = warpSum(s2);
    float mean = s1 / HIDW;
    float inv = rsqrtf(s2 / HIDW - mean * mean + 1e-5f);
    float* po = hbuf + (size_t)d * HIDW;
#pragma unroll
    for (int h = 0; h < NH; h++) {
        int c = h * HD + lane;
        float t = (acc[h] - mean) * inv * gamma[c] + beta[c];
        po[c] += gelu_exact(t);
    }
}

// ---------------- TransformerConv node kernel: softmax + aggregate + skip + LN + residual ----
__global__ void tr_node_kernel(const float* __restrict__ vfeat,
                               const float* __restrict__ sc,
                               const int* __restrict__ rowptr, const int* __restrict__ rowend,
                               const int* __restrict__ ecol, const int* __restrict__ esrc,
                               const float* __restrict__ skip,
                               const float* __restrict__ gamma, const float* __restrict__ beta,
                               float* __restrict__ hbuf)
{
    int d = (blockIdx.x * blockDim.x + threadIdx.x) >> 5;
    int lane = threadIdx.x & 31;
    if (d >= NN) return;
    int r0 = rowptr[d], r1 = rowend[d];

    float mx = -INFINITY;
    for (int i = r0; i < r1; i++) {
        int e = ecol[i];
        float v = sc[(size_t)e * NH + (lane & 7)];
        if (lane < NH) mx = fmaxf(mx, v);
    }
    float den = 0.f;
    float acc[NH];
#pragma unroll
    for (int h = 0; h < NH; h++) acc[h] = 0.f;
    for (int i = r0; i < r1; i++) {
        int e = ecol[i], s = esrc[i];
        float raw = sc[(size_t)e * NH + (lane & 7)];
        float ev = (lane < NH) ? expf(raw - mx) : 0.f;
        den += ev;
        const float* pv = vfeat + (size_t)s * HIDW;
#pragma unroll
        for (int h = 0; h < NH; h++)
            acc[h] += __shfl_sync(0xffffffffu, ev, h) * pv[h * HD + lane];
    }
    const float* psk = skip + (size_t)d * HIDW;
    float s1 = 0.f, s2 = 0.f;
#pragma unroll
    for (int h = 0; h < NH; h++) {
        float dh = __shfl_sync(0xffffffffu, den, h) + 1e-16f;
        float t = acc[h] / dh + psk[h * HD + lane];
        acc[h] = t; s1 += t; s2 += t * t;
    }
    s1 = warpSum(s1); s2 = warpSum(s2);
    float mean = s1 / HIDW;
    float inv = rsqrtf(s2 / HIDW - mean * mean + 1e-5f);
    float* po = hbuf + (size_t)d * HIDW;
#pragma unroll
    for (int h = 0; h < NH; h++) {
        int c = h * HD + lane;
        po[c] += (acc[h] - mean) * inv * gamma[c] + beta[c];
    }
}

// ---------------- pooling: block per graph, batch is sorted ----------------
__global__ void pool_kernel(const float* __restrict__ h, const int* __restrict__ batch,
                            float* __restrict__ ge)
{
    int g = blockIdx.x;
    int f = threadIdx.x;      // 256
    __shared__ int slo, shi;
    if (f == 0) {
        int lo = 0, hi = NN;
        while (lo < hi) { int mid = (lo + hi) >> 1; if (batch[mid] < g) lo = mid + 1; else hi = mid; }
        slo = lo;
        hi = NN;
        while (lo < hi) { int mid = (lo + hi) >> 1; if (batch[mid] < g + 1) lo = mid + 1; else hi = mid; }
        shi = lo;
    }
    __syncthreads();
    int lo = slo, hi = shi;
    float s = 0.f, mx = -INFINITY;
    for (int n = lo; n < hi; n++) {
        float v = h[(size_t)n * HIDW + f];
        s += v; mx = fmaxf(mx, v);
    }
    float cnt = (float)(hi - lo);
    ge[(size_t)g * (2 * HIDW) + f] = s / fmaxf(cnt, 1.f);
    ge[(size_t)g * (2 * HIDW) + HIDW + f] = isfinite(mx) ? mx : 0.f;
}

// skip-add before final LN is folded by doing LN on (agg+skip) inside tr_node; for
// the output projection the plain ln_act_kernel suffices.

// ---------------- host orchestration ----------------
extern "C" void kernel_launch(void* const* d_in, const int* in_sizes, int n_in,
                              void* d_out, int out_size)
{
    const float* x       = (const float*)d_in[0];
    const int*   ei      = (const int*)  d_in[1];
    const int*   batch   = (const int*)  d_in[2];
    const float* in_W    = (const float*)d_in[3];
    const float* in_b    = (const float*)d_in[4];
    const float* in_ln_g = (const float*)d_in[5];
    const float* in_ln_b = (const float*)d_in[6];
    const float* gat_Wl  = (const float*)d_in[7];
    const float* gat_bl  = (const float*)d_in[8];
    const float* gat_Wr  = (const float*)d_in[9];
    const float* gat_br  = (const float*)d_in[10];
    const float* gat_att = (const float*)d_in[11];
    const float* gat_bias= (const float*)d_in[12];
    const float* gat_ln_g= (const float*)d_in[13];
    const float* gat_ln_b= (const float*)d_in[14];
    const float* tr_Wq   = (const float*)d_in[15];
    const float* tr_bq   = (const float*)d_in[16];
    const float* tr_Wk   = (const float*)d_in[17];
    const float* tr_bk   = (const float*)d_in[18];
    const float* tr_Wv   = (const float*)d_in[19];
    const float* tr_bv   = (const float*)d_in[20];
    const float* tr_Wskip= (const float*)d_in[21];
    const float* tr_bskip= (const float*)d_in[22];
    const float* tr_ln_g = (const float*)d_in[23];
    const float* tr_ln_b = (const float*)d_in[24];
    const float* out_W   = (const float*)d_in[25];
    const float* out_b   = (const float*)d_in[26];
    const float* out_ln_g= (const float*)d_in[27];
    const float* out_ln_b= (const float*)d_in[28];

    const int* src = ei;
    const int* dst = ei + EE;

    float *h, *b1, *b2, *b3, *b4, *sc, *ge, *go;
    int *deg, *rowptr, *cur, *bsum, *ecol, *esrc;
    cudaGetSymbolAddress((void**)&h,   g_h);
    cudaGetSymbolAddress((void**)&b1,  g_b1);
    cudaGetSymbolAddress((void**)&b2,  g_b2);
    cudaGetSymbolAddress((void**)&b3,  g_b3);
    cudaGetSymbolAddress((void**)&b4,  g_b4);
    cudaGetSymbolAddress((void**)&sc,  g_sc);
    cudaGetSymbolAddress((void**)&ge,  g_ge);
    cudaGetSymbolAddress((void**)&go,  g_go);
    cudaGetSymbolAddress((void**)&deg,   g_deg);
    cudaGetSymbolAddress((void**)&rowptr,g_rowptr);
    cudaGetSymbolAddress((void**)&cur,   g_cur);
    cudaGetSymbolAddress((void**)&bsum,  g_bsum);
    cudaGetSymbolAddress((void**)&ecol,  g_ecol);
    cudaGetSymbolAddress((void**)&esrc,  g_esrc);

    const int ROW_WARPS_N = (NN * 32 + 255) / 256;
    const int EDGE_WARPS  = (EE * 32 + 255) / 256;
    const dim3 GEMM_GRID(HIDW / BN, (NN + BM - 1) / BM);

    // ---- CSR build (by destination) ----
    cudaMemsetAsync(deg, 0, NN * sizeof(int));
    hist_kernel  <<<(EE + 255) / 256, 256>>>(dst, deg);
    scan1_kernel <<<SNB, SCH>>>(deg, rowptr, bsum);
    scan2_kernel <<<1, 256>>>(bsum);
    scan3_kernel <<<(NN + 255) / 256, 256>>>(rowptr, bsum, cur);
    scatter_kernel<<<(EE + 255) / 256, 256>>>(src, dst, cur, ecol, esrc);

    // ---- input embedding: h = gelu(LN(x @ in_W + in_b)) ----
    gemm_bias<<<GEMM_GRID, 256>>>(x, in_W, in_b, b1, NN, FIN, HIDW);
    ln_act_kernel<<<ROW_WARPS_N, 256>>>(b1, in_ln_g, in_ln_b, h, NN, HIDW, 1);

    // ---- 5 GATv2 layers ----
    for (int l = 0; l < NL; l++) {
        const float* Wl = gat_Wl + (size_t)l * HIDW * HIDW;
        const float* Wr = gat_Wr + (size_t)l * HIDW * HIDW;
        gemm_bias<<<GEMM_GRID, 256>>>(h, Wl, gat_bl + l * HIDW, b1, NN, HIDW, HIDW);
        gemm_bias<<<GEMM_GRID, 256>>>(h, Wr, gat_br + l * HIDW, b2, NN, HIDW, HIDW);
        gat_score_kernel<<<EDGE_WARPS, 256>>>(b1, b2, src, dst,
                                              gat_att + (size_t)l * NH * HD, sc);
        gat_node_kernel<<<ROW_WARPS_N, 256>>>(b1, b2, sc, rowptr, cur, ecol, esrc,
                                              gat_att + (size_t)l * NH * HD,
                                              gat_bias + l * HIDW,
                                              gat_ln_g + l * HIDW, gat_ln_b + l * HIDW,
                                              h);
    }

    // ---- TransformerConv ----
    gemm_bias<<<GEMM_GRID, 256>>>(h, tr_Wq, tr_bq, b1, NN, HIDW, HIDW);
    gemm_bias<<<GEMM_GRID, 256>>>(h, tr_Wk, tr_bk, b2, NN, HIDW, HIDW);
    gemm_bias<<<GEMM_GRID, 256>>>(h, tr_Wv, tr_bv, b3, NN, HIDW, HIDW);
    gemm_bias<<<GEMM_GRID, 256>>>(h, tr_Wskip, tr_bskip, b4, NN, HIDW, HIDW);
    tr_score_kernel<<<EDGE_WARPS, 256>>>(b1, b2, src, dst, sc);
    tr_node_kernel<<<ROW_WARPS_N, 256>>>(b3, sc, rowptr, cur, ecol, esrc,
                                         b4, tr_ln_g, tr_ln_b, h);

    // ---- global mean + max pool (batch sorted; block per graph) ----
    pool_kernel<<<GG, 256>>>(h, batch, ge);

    // ---- output projection: gelu(LN(ge @ out_W + out_b)) ----
    gemm_bias<<<dim3(2 * HIDW / BN, (GG + BM - 1) / BM), 256>>>(ge, out_W, out_b, go,
                                                                GG, 2 * HIDW, 2 * HIDW);
    ln_act_kernel<<<(GG * 32 + 255) / 256, 256>>>(go, out_ln_g, out_ln_b,
                                                  (float*)d_out, GG, 2 * HIDW, 1);
}